// round 15
// baseline (speedup 1.0000x reference)
#include <cuda_runtime.h>
#include <cuda_bf16.h>

#define HDIM 2048
#define NBS 40        // B*S
#define BB 4
#define LL 4096
#define SS 10
#define SCALE 0.022097086912079608f  // 1/sqrt(2048)

// scratch layout (float offsets). Tensor = 40*2048 = 81920 floats.
#define TEN 81920
#define OFF_KVEC 0
#define OFF_VVEC (1 * TEN)
#define OFF_VO   (2 * TEN)
#define OFF_KK   (3 * TEN)
#define OFF_P1   (4 * TEN)               // phase1 partials: 2 mats x 8 ks x TEN
#define OFF_P2VO (OFF_P1 + 16 * TEN)     // vo partials: 8 x TEN
#define OFF_P2KK (OFF_P2VO + 8 * TEN)    // kk partials: 8 x TEN

__device__ __align__(16) float g_scratch[OFF_P2KK + 8 * TEN];

typedef unsigned long long u64;
typedef unsigned int u32;

// ---- scalar helpers --------------------------------------------------------
__device__ __forceinline__ u64 ffma2(u64 a, u64 b, u64 c) {
    u64 d;
    asm("fma.rn.f32x2 %0, %1, %2, %3;" : "=l"(d) : "l"(a), "l"(b), "l"(c));
    return d;
}
__device__ __forceinline__ u64 pack2(float lo, float hi) {
    u64 r;
    asm("mov.b64 %0, {%1, %2};" : "=l"(r) : "f"(lo), "f"(hi));
    return r;
}
__device__ __forceinline__ float hsum2(u64 v) {
    float lo, hi;
    asm("mov.b64 {%0, %1}, %2;" : "=f"(lo), "=f"(hi) : "l"(v));
    return lo + hi;
}
__device__ __forceinline__ float warp_sum(float v) {
    v += __shfl_xor_sync(0xffffffffu, v, 16);
    v += __shfl_xor_sync(0xffffffffu, v, 8);
    v += __shfl_xor_sync(0xffffffffu, v, 4);
    v += __shfl_xor_sync(0xffffffffu, v, 2);
    v += __shfl_xor_sync(0xffffffffu, v, 1);
    return v;
}
__device__ __forceinline__ void stcs16(float* p, u64 a, u64 b) {
    asm volatile("st.global.cs.v2.b64 [%0], {%1, %2};" :: "l"(p), "l"(a), "l"(b) : "memory");
}

// ---- mma.sync / ldmatrix plumbing (plain PTX) ------------------------------
__device__ __forceinline__ u32 s2u(const void* p) {
    u32 a;
    asm("{ .reg .u64 t; cvta.to.shared.u64 t, %1; cvt.u32.u64 %0, t; }" : "=r"(a) : "l"(p));
    return a;
}
__device__ __forceinline__ void ldm_x4(u32& r0, u32& r1, u32& r2, u32& r3, u32 addr) {
    asm volatile("ldmatrix.sync.aligned.m8n8.x4.shared.b16 {%0,%1,%2,%3}, [%4];"
                 : "=r"(r0), "=r"(r1), "=r"(r2), "=r"(r3) : "r"(addr));
}
__device__ __forceinline__ void ldm_x2(u32& r0, u32& r1, u32 addr) {
    asm volatile("ldmatrix.sync.aligned.m8n8.x2.shared.b16 {%0,%1}, [%2];"
                 : "=r"(r0), "=r"(r1) : "r"(addr));
}
__device__ __forceinline__ void mma_bf16(float* d, u32 a0, u32 a1, u32 a2, u32 a3,
                                         u32 b0, u32 b1) {
    asm volatile("mma.sync.aligned.m16n8k16.row.col.f32.bf16.bf16.f32 "
                 "{%0,%1,%2,%3}, {%4,%5,%6,%7}, {%8,%9}, {%0,%1,%2,%3};"
                 : "+f"(d[0]), "+f"(d[1]), "+f"(d[2]), "+f"(d[3])
                 : "r"(a0), "r"(a1), "r"(a2), "r"(a3), "r"(b0), "r"(b1));
}

// smem tile layout (bytes). Row stride 272 B: 16B-aligned, conflict-free ldmatrix.
#define RS_B 272
#define SM_WHI 0
#define SM_WLO (SM_WHI + 128 * RS_B)
#define SM_YHI (SM_WLO + 128 * RS_B)
#define SM_YLO (SM_YHI + 40 * RS_B)
#define SM_TOT (SM_YLO + 40 * RS_B)      // 91392 -> 2 CTA/SM

// stage k-major fp32 [nrows x 128] slice -> hi/lo bf16 tiles
__device__ __forceinline__ void stage_km(const float* __restrict__ S, int row0, int nrows,
                                         int k0, char* smem, int hi_off, int lo_off)
{
    for (int idx = threadIdx.x; idx < nrows * 32; idx += 256) {
        int rr = idx >> 5, c4 = idx & 31;
        float4 v = *reinterpret_cast<const float4*>(S + (size_t)(row0 + rr) * HDIM + k0 + c4 * 4);
        __nv_bfloat162 h01 = __floats2bfloat162_rn(v.x, v.y);
        __nv_bfloat162 h23 = __floats2bfloat162_rn(v.z, v.w);
        float2 f01 = __bfloat1622float2(h01);
        float2 f23 = __bfloat1622float2(h23);
        __nv_bfloat162 l01 = __floats2bfloat162_rn(v.x - f01.x, v.y - f01.y);
        __nv_bfloat162 l23 = __floats2bfloat162_rn(v.z - f23.x, v.w - f23.y);
        int byt = rr * RS_B + c4 * 8;
        *reinterpret_cast<__nv_bfloat162*>(smem + hi_off + byt)     = h01;
        *reinterpret_cast<__nv_bfloat162*>(smem + hi_off + byt + 4) = h23;
        *reinterpret_cast<__nv_bfloat162*>(smem + lo_off + byt)     = l01;
        *reinterpret_cast<__nv_bfloat162*>(smem + lo_off + byt + 4) = l23;
    }
}

// stage TRANSPOSED A for kk: tile[m_local][k_local] = Wq[k0+k_local][m0+m_local]
__device__ __forceinline__ void stage_tr(const float* __restrict__ S, int m0, int k0,
                                         char* smem)
{
    for (int idx = threadIdx.x; idx < 128 * 32; idx += 256) {
        int ol = idx >> 5, i4 = idx & 31;
        float4 v = *reinterpret_cast<const float4*>(S + (size_t)(k0 + ol) * HDIM + m0 + i4 * 4);
        float vv[4] = {v.x, v.y, v.z, v.w};
#pragma unroll
        for (int j = 0; j < 4; j++) {
            __nv_bfloat16 h = __float2bfloat16(vv[j]);
            __nv_bfloat16 l = __float2bfloat16(vv[j] - __bfloat162float(h));
            int byt = (i4 * 4 + j) * RS_B + ol * 2;
            *reinterpret_cast<__nv_bfloat16*>(smem + SM_WHI + byt) = h;
            *reinterpret_cast<__nv_bfloat16*>(smem + SM_WLO + byt) = l;
        }
    }
}

// ---------------------------------------------------------------------------
// HMMA GEMM body: P[bs][m0..m0+127] = sum_{k in [kb,kb+256)} A[m][k]*B[bs][k]
// Two staged 128-k chunks; warp owns 16 m-rows; 5 n-tiles cover 40 bs;
// 3-product split bf16 (hi*hi + hi*lo + lo*hi), fp32 accum.
// ---------------------------------------------------------------------------
__device__ void mma_gemm(const float* __restrict__ A, const float* __restrict__ Bsrc,
                         float* __restrict__ P, int m0, int kb, bool transA)
{
    extern __shared__ __align__(16) char smem[];
    u32 sb = s2u(smem);
    int tid = threadIdx.x, wid = tid >> 5, lane = tid & 31;

    // per-lane ldmatrix addresses (smem layout constant across k-chunks)
    int amrow = (lane & 7) + ((lane >> 3) & 1) * 8;
    int akb   = (lane >> 4) * 16;
    u32 ahi = sb + SM_WHI + (u32)((wid * 16 + amrow) * RS_B + akb);
    u32 alo = ahi + (SM_WLO - SM_WHI);
    int bmrow = lane & 7;
    int bkb   = ((lane >> 3) & 1) * 16;
    u32 bhi = sb + SM_YHI + (u32)(bmrow * RS_B + bkb);
    u32 blo = bhi + (SM_YLO - SM_YHI);

    float acc[5][4];
#pragma unroll
    for (int nt = 0; nt < 5; nt++)
#pragma unroll
        for (int j = 0; j < 4; j++) acc[nt][j] = 0.f;

    for (int kc = 0; kc < 2; kc++) {
        int k0 = kb + kc * 128;
        if (kc) __syncthreads();
        if (!transA) stage_km(A, m0, 128, k0, smem, SM_WHI, SM_WLO);
        else         stage_tr(A, m0, k0, smem);
        stage_km(Bsrc, 0, 40, k0, smem, SM_YHI, SM_YLO);
        __syncthreads();

#pragma unroll
        for (int kt = 0; kt < 8; kt++) {
            u32 A0h, A1h, A2h, A3h, A0l, A1l, A2l, A3l;
            ldm_x4(A0h, A1h, A2h, A3h, ahi + kt * 32);
            ldm_x4(A0l, A1l, A2l, A3l, alo + kt * 32);
#pragma unroll
            for (int nt = 0; nt < 5; nt++) {
                u32 b0h, b1h, b0l, b1l;
                ldm_x2(b0h, b1h, bhi + nt * (8 * RS_B) + kt * 32);
                ldm_x2(b0l, b1l, blo + nt * (8 * RS_B) + kt * 32);
                mma_bf16(acc[nt], A0h, A1h, A2h, A3h, b0h, b1h);
                mma_bf16(acc[nt], A0h, A1h, A2h, A3h, b0l, b1l);
                mma_bf16(acc[nt], A0l, A1l, A2l, A3l, b0h, b1h);
            }
        }
    }

    int g = lane >> 2, tc = lane & 3;
    int om = m0 + wid * 16 + g;
#pragma unroll
    for (int nt = 0; nt < 5; nt++) {
        int bs0 = nt * 8 + 2 * tc;
        P[(size_t)bs0 * HDIM + om]           = acc[nt][0];
        P[(size_t)(bs0 + 1) * HDIM + om]     = acc[nt][1];
        P[(size_t)bs0 * HDIM + om + 8]       = acc[nt][2];
        P[(size_t)(bs0 + 1) * HDIM + om + 8] = acc[nt][3];
    }
}

// Phase 1: 256 blocks. mat = bid>>7; r&15 = m-tile, r>>4 = k-split (8 x 256k).
__global__ void __launch_bounds__(256, 2) prep1_mma(const float* __restrict__ Wk,
                                                    const float* __restrict__ Wv,
                                                    const float* __restrict__ Y)
{
    int mat = blockIdx.x >> 7;
    int r = blockIdx.x & 127;
    int m0 = (r & 15) * 128;
    int ks = r >> 4;
    const float* W = mat ? Wv : Wk;
    float* P = g_scratch + OFF_P1 + (size_t)mat * (8 * TEN) + (size_t)ks * TEN;
    mma_gemm(W, Y, P, m0, ks * 256, false);
}

// Phase 2: 256 blocks. half 0: vo = vvec @ Wo^T; half 1: kk = kvec @ Wq (transA).
__global__ void __launch_bounds__(256, 2) prep2_mma(const float* __restrict__ Wo,
                                                    const float* __restrict__ Wq)
{
    int half = blockIdx.x >> 7;
    int r = blockIdx.x & 127;
    int m0 = (r & 15) * 128;
    int ks = r >> 4;
    if (half == 0)
        mma_gemm(Wo, g_scratch + OFF_VVEC, g_scratch + OFF_P2VO + (size_t)ks * TEN,
                 m0, ks * 256, false);
    else
        mma_gemm(Wq, g_scratch + OFF_KVEC, g_scratch + OFF_P2KK + (size_t)ks * TEN,
                 m0, ks * 256, true);
}

// reduce phase-1 partials (8 splits) -> kvec, vvec
__global__ void __launch_bounds__(256) reduce1_kernel()
{
    int gid = blockIdx.x * 256 + threadIdx.x;
    int which = gid >= (TEN / 4);
    int e = gid - which * (TEN / 4);
    const float4* src = reinterpret_cast<const float4*>(
        g_scratch + OFF_P1 + (size_t)which * (8 * TEN));
    float4 s = make_float4(0.f, 0.f, 0.f, 0.f);
#pragma unroll
    for (int ks = 0; ks < 8; ks++) {
        float4 p = src[(size_t)ks * (TEN / 4) + e];
        s.x += p.x; s.y += p.y; s.z += p.z; s.w += p.w;
    }
    reinterpret_cast<float4*>(g_scratch + (which ? OFF_VVEC : OFF_KVEC))[e] = s;
}

// reduce phase-2 partials (8 splits) -> vo, kk (kk folds 1/sqrt(H))
__global__ void __launch_bounds__(256) reduce2_kernel()
{
    int gid = blockIdx.x * 256 + threadIdx.x;
    int which = gid >= (TEN / 4);
    int e = gid - which * (TEN / 4);
    const float4* src = reinterpret_cast<const float4*>(
        g_scratch + (which ? OFF_P2KK : OFF_P2VO));
    float4 s = make_float4(0.f, 0.f, 0.f, 0.f);
#pragma unroll
    for (int ks = 0; ks < 8; ks++) {
        float4 p = src[(size_t)ks * (TEN / 4) + e];
        s.x += p.x; s.y += p.y; s.z += p.z; s.w += p.w;
    }
    if (which) { s.x *= SCALE; s.y *= SCALE; s.z *= SCALE; s.w *= SCALE; }
    reinterpret_cast<float4*>(g_scratch + (which ? OFF_KK : OFF_VO))[e] = s;
}

// ---------------------------------------------------------------------------
// Main fused kernel v2: 1 row/warp, full X row register-cached (no stage-B
// re-read). 512 thr, kk+vo resident in 160 KB smem filled once; each block
// loops 4 row-groups (64 rows). Grid (64, 4) = 256 blocks.
// ---------------------------------------------------------------------------
__global__ void __launch_bounds__(512, 1) main_kernel(const float* __restrict__ X,
                                                      const float* __restrict__ alpha_p,
                                                      float* __restrict__ out)
{
    extern __shared__ __align__(16) float sm[];
    float* skk = sm;
    float* svo = sm + SS * HDIM;

    int b = blockIdx.y;
    const float* kkb = g_scratch + OFF_KK + (size_t)b * SS * HDIM;
    const float* vob = g_scratch + OFF_VO + (size_t)b * SS * HDIM;

    for (int idx = threadIdx.x; idx < SS * HDIM / 4; idx += 512) {
        reinterpret_cast<float4*>(skk)[idx] = reinterpret_cast<const float4*>(kkb)[idx];
        reinterpret_cast<float4*>(svo)[idx] = reinterpret_cast<const float4*>(vob)[idx];
    }
    float alpha = *alpha_p;
    __syncthreads();

    int warp = threadIdx.x >> 5;
    int lane = threadIdx.x & 31;

    for (int it = 0; it < 4; it++) {
        int row = blockIdx.x * 64 + it * 16 + warp;
        const float* xr = X + ((size_t)b * LL + row) * HDIM;
        float* orow = out + ((size_t)b * LL + row) * HDIM;

        // prefetch full row into registers: 16 independent LDG.128
        u64 xg[32];
#pragma unroll
        for (int c = 0; c < 16; c++) {
            ulonglong2 v = *reinterpret_cast<const ulonglong2*>(xr + c * 128 + lane * 4);
            xg[2 * c]     = v.x;
            xg[2 * c + 1] = v.y;
        }

        // stage A: scores from registers x smem kk
        u64 acc[SS];
#pragma unroll
        for (int s = 0; s < SS; s++) acc[s] = 0ull;
#pragma unroll
        for (int c = 0; c < 16; c++) {
            int h = c * 128 + lane * 4;
#pragma unroll
            for (int s = 0; s < SS; s++) {
                ulonglong2 k2 = *reinterpret_cast<const ulonglong2*>(skk + s * HDIM + h);
                acc[s] = ffma2(xg[2 * c], k2.x, acc[s]);
                acc[s] = ffma2(xg[2 * c + 1], k2.y, acc[s]);
            }
        }

        float p[SS];
#pragma unroll
        for (int s = 0; s < SS; s++) p[s] = warp_sum(hsum2(acc[s]));

        float m = p[0];
#pragma unroll
        for (int s = 1; s < SS; s++) m = fmaxf(m, p[s]);
        float sum = 0.f;
#pragma unroll
        for (int s = 0; s < SS; s++) {
            float e = __expf(p[s] - m);
            p[s] = e;
            sum += e;
        }
        float inv = alpha / sum;
        u64 pp[SS];
#pragma unroll
        for (int s = 0; s < SS; s++) {
            float v = p[s] * inv;
            pp[s] = pack2(v, v);
        }

        // stage B: out = x + sum_s p_s * vo_s  (x from registers; streaming store)
#pragma unroll
        for (int c = 0; c < 16; c++) {
            int h = c * 128 + lane * 4;
            u64 yx = xg[2 * c], yy = xg[2 * c + 1];
#pragma unroll
            for (int s = 0; s < SS; s++) {
                ulonglong2 v2 = *reinterpret_cast<const ulonglong2*>(svo + s * HDIM + h);
                yx = ffma2(pp[s], v2.x, yx);
                yy = ffma2(pp[s], v2.y, yy);
            }
            stcs16(orow + h, yx, yy);
        }
    }
}

extern "C" void kernel_launch(void* const* d_in, const int* in_sizes, int n_in,
                              void* d_out, int out_size)
{
    const float* x     = (const float*)d_in[0];  // h_english [4,4096,2048]
    const float* y     = (const float*)d_in[1];  // h_lojban  [4,10,2048]
    const float* wq    = (const float*)d_in[2];
    const float* wk    = (const float*)d_in[3];
    const float* wv    = (const float*)d_in[4];
    const float* wo    = (const float*)d_in[5];
    const float* alpha = (const float*)d_in[6];
    float* out = (float*)d_out;

    (void)cudaFuncSetAttribute(prep1_mma, cudaFuncAttributeMaxDynamicSharedMemorySize, SM_TOT);
    (void)cudaFuncSetAttribute(prep2_mma, cudaFuncAttributeMaxDynamicSharedMemorySize, SM_TOT);
    (void)cudaFuncSetAttribute(main_kernel, cudaFuncAttributeMaxDynamicSharedMemorySize,
                               2 * SS * HDIM * (int)sizeof(float));

    // Phase 1 (HMMA): kvec/vvec partials (8 k-splits), then reduce
    prep1_mma<<<256, 256, SM_TOT>>>(wk, wv, y);
    reduce1_kernel<<<2 * (TEN / 4) / 256, 256>>>();
    // Phase 2 (HMMA): vo partials + kk partials, then reduce (+scale)
    prep2_mma<<<256, 256, SM_TOT>>>(wo, wq);
    reduce2_kernel<<<2 * (TEN / 4) / 256, 256>>>();
    // Fused attention-apply: X register-cached, single DRAM read + write
    main_kernel<<<dim3(LL / 64, BB), 512, 2 * SS * HDIM * sizeof(float)>>>(x, alpha, out);
}

// round 16
// speedup vs baseline: 1.2159x; 1.2159x over previous
#include <cuda_runtime.h>
#include <cuda_bf16.h>

#define HDIM 2048
#define NBS 40        // B*S
#define BB 4
#define LL 4096
#define SS 10
#define SCALE 0.022097086912079608f  // 1/sqrt(2048)

// scratch layout (float offsets). Tensor = 40*2048 = 81920 floats.
#define TEN 81920
#define OFF_KVEC 0
#define OFF_VVEC (1 * TEN)
#define OFF_VO   (2 * TEN)
#define OFF_KK   (3 * TEN)
#define OFF_P1   (4 * TEN)               // phase1 partials: 2 mats x 8 ks x TEN
#define OFF_P2VO (OFF_P1 + 16 * TEN)     // vo partials: 8 x TEN
#define OFF_P2KK (OFF_P2VO + 8 * TEN)    // kk partials: 8 x TEN

__device__ __align__(16) float g_scratch[OFF_P2KK + 8 * TEN];

typedef unsigned long long u64;
typedef unsigned int u32;

// ---- scalar helpers --------------------------------------------------------
__device__ __forceinline__ u64 ffma2(u64 a, u64 b, u64 c) {
    u64 d;
    asm("fma.rn.f32x2 %0, %1, %2, %3;" : "=l"(d) : "l"(a), "l"(b), "l"(c));
    return d;
}
__device__ __forceinline__ u64 pack2(float lo, float hi) {
    u64 r;
    asm("mov.b64 %0, {%1, %2};" : "=l"(r) : "f"(lo), "f"(hi));
    return r;
}
__device__ __forceinline__ float hsum2(u64 v) {
    float lo, hi;
    asm("mov.b64 {%0, %1}, %2;" : "=f"(lo), "=f"(hi) : "l"(v));
    return lo + hi;
}
__device__ __forceinline__ float warp_sum(float v) {
    v += __shfl_xor_sync(0xffffffffu, v, 16);
    v += __shfl_xor_sync(0xffffffffu, v, 8);
    v += __shfl_xor_sync(0xffffffffu, v, 4);
    v += __shfl_xor_sync(0xffffffffu, v, 2);
    v += __shfl_xor_sync(0xffffffffu, v, 1);
    return v;
}
__device__ __forceinline__ void stcs16(float* p, ulonglong2 v) {
    asm volatile("st.global.cs.v2.b64 [%0], {%1, %2};" :: "l"(p), "l"(v.x), "l"(v.y) : "memory");
}

// ---- mma.sync / ldmatrix plumbing (plain PTX) ------------------------------
__device__ __forceinline__ u32 s2u(const void* p) {
    u32 a;
    asm("{ .reg .u64 t; cvta.to.shared.u64 t, %1; cvt.u32.u64 %0, t; }" : "=r"(a) : "l"(p));
    return a;
}
__device__ __forceinline__ void ldm_x4(u32& r0, u32& r1, u32& r2, u32& r3, u32 addr) {
    asm volatile("ldmatrix.sync.aligned.m8n8.x4.shared.b16 {%0,%1,%2,%3}, [%4];"
                 : "=r"(r0), "=r"(r1), "=r"(r2), "=r"(r3) : "r"(addr));
}
__device__ __forceinline__ void ldm_x2(u32& r0, u32& r1, u32 addr) {
    asm volatile("ldmatrix.sync.aligned.m8n8.x2.shared.b16 {%0,%1}, [%2];"
                 : "=r"(r0), "=r"(r1) : "r"(addr));
}
__device__ __forceinline__ void mma_bf16(float* d, u32 a0, u32 a1, u32 a2, u32 a3,
                                         u32 b0, u32 b1) {
    asm volatile("mma.sync.aligned.m16n8k16.row.col.f32.bf16.bf16.f32 "
                 "{%0,%1,%2,%3}, {%4,%5,%6,%7}, {%8,%9}, {%0,%1,%2,%3};"
                 : "+f"(d[0]), "+f"(d[1]), "+f"(d[2]), "+f"(d[3])
                 : "r"(a0), "r"(a1), "r"(a2), "r"(a3), "r"(b0), "r"(b1));
}

// smem tile layout (bytes). Row stride 272 B: 16B-aligned, conflict-free ldmatrix.
#define RS_B 272
#define SM_WHI 0
#define SM_WLO (SM_WHI + 128 * RS_B)
#define SM_YHI (SM_WLO + 128 * RS_B)
#define SM_YLO (SM_YHI + 40 * RS_B)
#define SM_TOT (SM_YLO + 40 * RS_B)      // 91392 -> 2 CTA/SM
// epilogue bounce buffer (reuses tile area): 40 x 132 floats, stride-132 pad
#define EP_STRIDE 132

// stage k-major fp32 [nrows x 128] slice -> hi/lo bf16 tiles
__device__ __forceinline__ void stage_km(const float* __restrict__ S, int row0, int nrows,
                                         int k0, char* smem, int hi_off, int lo_off)
{
    for (int idx = threadIdx.x; idx < nrows * 32; idx += 256) {
        int rr = idx >> 5, c4 = idx & 31;
        float4 v = *reinterpret_cast<const float4*>(S + (size_t)(row0 + rr) * HDIM + k0 + c4 * 4);
        __nv_bfloat162 h01 = __floats2bfloat162_rn(v.x, v.y);
        __nv_bfloat162 h23 = __floats2bfloat162_rn(v.z, v.w);
        float2 f01 = __bfloat1622float2(h01);
        float2 f23 = __bfloat1622float2(h23);
        __nv_bfloat162 l01 = __floats2bfloat162_rn(v.x - f01.x, v.y - f01.y);
        __nv_bfloat162 l23 = __floats2bfloat162_rn(v.z - f23.x, v.w - f23.y);
        int byt = rr * RS_B + c4 * 8;
        *reinterpret_cast<__nv_bfloat162*>(smem + hi_off + byt)     = h01;
        *reinterpret_cast<__nv_bfloat162*>(smem + hi_off + byt + 4) = h23;
        *reinterpret_cast<__nv_bfloat162*>(smem + lo_off + byt)     = l01;
        *reinterpret_cast<__nv_bfloat162*>(smem + lo_off + byt + 4) = l23;
    }
}

// stage TRANSPOSED A for kk: tile[m_local][k_local] = Wq[k0+k_local][m0+m_local]
__device__ __forceinline__ void stage_tr(const float* __restrict__ S, int m0, int k0,
                                         char* smem)
{
    for (int idx = threadIdx.x; idx < 128 * 32; idx += 256) {
        int ol = idx >> 5, i4 = idx & 31;
        float4 v = *reinterpret_cast<const float4*>(S + (size_t)(k0 + ol) * HDIM + m0 + i4 * 4);
        float vv[4] = {v.x, v.y, v.z, v.w};
#pragma unroll
        for (int j = 0; j < 4; j++) {
            __nv_bfloat16 h = __float2bfloat16(vv[j]);
            __nv_bfloat16 l = __float2bfloat16(vv[j] - __bfloat162float(h));
            int byt = (i4 * 4 + j) * RS_B + ol * 2;
            *reinterpret_cast<__nv_bfloat16*>(smem + SM_WHI + byt) = h;
            *reinterpret_cast<__nv_bfloat16*>(smem + SM_WLO + byt) = l;
        }
    }
}

// ---------------------------------------------------------------------------
// HMMA GEMM body: P[bs][m0..m0+127] = sum_{k in [kb,kb+256)} A[m][k]*B[bs][k]
// Two staged 128-k chunks; warp owns 16 m-rows; 5 n-tiles cover 40 bs;
// 3-product split bf16 (hi*hi + hi*lo + lo*hi), fp32 accum.
// Epilogue bounces D through smem for fully-coalesced partial stores.
// ---------------------------------------------------------------------------
__device__ void mma_gemm(const float* __restrict__ A, const float* __restrict__ Bsrc,
                         float* __restrict__ P, int m0, int kb, bool transA)
{
    extern __shared__ __align__(16) char smem[];
    u32 sb = s2u(smem);
    int tid = threadIdx.x, wid = tid >> 5, lane = tid & 31;

    // per-lane ldmatrix addresses (smem layout constant across k-chunks)
    int amrow = (lane & 7) + ((lane >> 3) & 1) * 8;
    int akb   = (lane >> 4) * 16;
    u32 ahi = sb + SM_WHI + (u32)((wid * 16 + amrow) * RS_B + akb);
    u32 alo = ahi + (SM_WLO - SM_WHI);
    int bmrow = lane & 7;
    int bkb   = ((lane >> 3) & 1) * 16;
    u32 bhi = sb + SM_YHI + (u32)(bmrow * RS_B + bkb);
    u32 blo = bhi + (SM_YLO - SM_YHI);

    float acc[5][4];
#pragma unroll
    for (int nt = 0; nt < 5; nt++)
#pragma unroll
        for (int j = 0; j < 4; j++) acc[nt][j] = 0.f;

    for (int kc = 0; kc < 2; kc++) {
        int k0 = kb + kc * 128;
        if (kc) __syncthreads();
        if (!transA) stage_km(A, m0, 128, k0, smem, SM_WHI, SM_WLO);
        else         stage_tr(A, m0, k0, smem);
        stage_km(Bsrc, 0, 40, k0, smem, SM_YHI, SM_YLO);
        __syncthreads();

#pragma unroll
        for (int kt = 0; kt < 8; kt++) {
            u32 A0h, A1h, A2h, A3h, A0l, A1l, A2l, A3l;
            ldm_x4(A0h, A1h, A2h, A3h, ahi + kt * 32);
            ldm_x4(A0l, A1l, A2l, A3l, alo + kt * 32);
#pragma unroll
            for (int nt = 0; nt < 5; nt++) {
                u32 b0h, b1h, b0l, b1l;
                ldm_x2(b0h, b1h, bhi + nt * (8 * RS_B) + kt * 32);
                ldm_x2(b0l, b1l, blo + nt * (8 * RS_B) + kt * 32);
                mma_bf16(acc[nt], A0h, A1h, A2h, A3h, b0h, b1h);
                mma_bf16(acc[nt], A0h, A1h, A2h, A3h, b0l, b1l);
                mma_bf16(acc[nt], A0l, A1l, A2l, A3l, b0h, b1h);
            }
        }
    }

    // epilogue: bounce D through smem (stride-132 pad: banks 8*tc+g, conflict-free),
    // then fully-coalesced 128-float-run stores to the partial tensor.
    __syncthreads();   // all warps done reading tiles before overwrite
    float* ep = reinterpret_cast<float*>(smem);
    int g = lane >> 2, tc = lane & 3;
    int oml = wid * 16 + g;
#pragma unroll
    for (int nt = 0; nt < 5; nt++) {
        int bs0 = nt * 8 + 2 * tc;
        ep[bs0 * EP_STRIDE + oml]             = acc[nt][0];
        ep[(bs0 + 1) * EP_STRIDE + oml]       = acc[nt][1];
        ep[bs0 * EP_STRIDE + oml + 8]         = acc[nt][2];
        ep[(bs0 + 1) * EP_STRIDE + oml + 8]   = acc[nt][3];
    }
    __syncthreads();
    for (int idx = tid; idx < 40 * 128; idx += 256) {
        int bs = idx >> 7, om = idx & 127;
        P[(size_t)bs * HDIM + m0 + om] = ep[bs * EP_STRIDE + om];
    }
}

// Phase 1: 256 blocks. mat = bid>>7; r&15 = m-tile, r>>4 = k-split (8 x 256k).
__global__ void __launch_bounds__(256, 2) prep1_mma(const float* __restrict__ Wk,
                                                    const float* __restrict__ Wv,
                                                    const float* __restrict__ Y)
{
    int mat = blockIdx.x >> 7;
    int r = blockIdx.x & 127;
    int m0 = (r & 15) * 128;
    int ks = r >> 4;
    const float* W = mat ? Wv : Wk;
    float* P = g_scratch + OFF_P1 + (size_t)mat * (8 * TEN) + (size_t)ks * TEN;
    mma_gemm(W, Y, P, m0, ks * 256, false);
}

// Phase 2: 256 blocks. half 0: vo = vvec @ Wo^T; half 1: kk = kvec @ Wq (transA).
__global__ void __launch_bounds__(256, 2) prep2_mma(const float* __restrict__ Wo,
                                                    const float* __restrict__ Wq)
{
    int half = blockIdx.x >> 7;
    int r = blockIdx.x & 127;
    int m0 = (r & 15) * 128;
    int ks = r >> 4;
    if (half == 0)
        mma_gemm(Wo, g_scratch + OFF_VVEC, g_scratch + OFF_P2VO + (size_t)ks * TEN,
                 m0, ks * 256, false);
    else
        mma_gemm(Wq, g_scratch + OFF_KVEC, g_scratch + OFF_P2KK + (size_t)ks * TEN,
                 m0, ks * 256, true);
}

// reduce phase-1 partials (8 splits) -> kvec, vvec
__global__ void __launch_bounds__(256) reduce1_kernel()
{
    int gid = blockIdx.x * 256 + threadIdx.x;
    int which = gid >= (TEN / 4);
    int e = gid - which * (TEN / 4);
    const float4* src = reinterpret_cast<const float4*>(
        g_scratch + OFF_P1 + (size_t)which * (8 * TEN));
    float4 s = make_float4(0.f, 0.f, 0.f, 0.f);
#pragma unroll
    for (int ks = 0; ks < 8; ks++) {
        float4 p = src[(size_t)ks * (TEN / 4) + e];
        s.x += p.x; s.y += p.y; s.z += p.z; s.w += p.w;
    }
    reinterpret_cast<float4*>(g_scratch + (which ? OFF_VVEC : OFF_KVEC))[e] = s;
}

// reduce phase-2 partials (8 splits) -> vo, kk (kk folds 1/sqrt(H))
__global__ void __launch_bounds__(256) reduce2_kernel()
{
    int gid = blockIdx.x * 256 + threadIdx.x;
    int which = gid >= (TEN / 4);
    int e = gid - which * (TEN / 4);
    const float4* src = reinterpret_cast<const float4*>(
        g_scratch + (which ? OFF_P2KK : OFF_P2VO));
    float4 s = make_float4(0.f, 0.f, 0.f, 0.f);
#pragma unroll
    for (int ks = 0; ks < 8; ks++) {
        float4 p = src[(size_t)ks * (TEN / 4) + e];
        s.x += p.x; s.y += p.y; s.z += p.z; s.w += p.w;
    }
    if (which) { s.x *= SCALE; s.y *= SCALE; s.z *= SCALE; s.w *= SCALE; }
    reinterpret_cast<float4*>(g_scratch + (which ? OFF_KK : OFF_VO))[e] = s;
}

// ---------------------------------------------------------------------------
// Main fused kernel (exact R14 config — measured 82.4us):
//   512 thr, 4 rows/warp, kk/vo (160 KB) resident in shared, grid (64, 4).
//   scores_s = x_l . kk[b][s]; p = softmax; out = x + sum_s p_s * vo[b][s]
// ---------------------------------------------------------------------------
__global__ void __launch_bounds__(512, 1) main_kernel(const float* __restrict__ X,
                                                      const float* __restrict__ alpha_p,
                                                      float* __restrict__ out)
{
    extern __shared__ __align__(16) float sm[];
    float* skk = sm;
    float* svo = sm + SS * HDIM;

    int b = blockIdx.y;
    const float* kkb = g_scratch + OFF_KK + (size_t)b * SS * HDIM;
    const float* vob = g_scratch + OFF_VO + (size_t)b * SS * HDIM;

    for (int idx = threadIdx.x; idx < SS * HDIM / 4; idx += 512) {
        reinterpret_cast<float4*>(skk)[idx] = reinterpret_cast<const float4*>(kkb)[idx];
        reinterpret_cast<float4*>(svo)[idx] = reinterpret_cast<const float4*>(vob)[idx];
    }
    float alpha = *alpha_p;
    __syncthreads();

    int warp = threadIdx.x >> 5;
    int lane = threadIdx.x & 31;
    int row0 = blockIdx.x * 64 + warp * 4;
    const float* xr = X + ((size_t)b * LL + row0) * HDIM;
    float* orow = out + ((size_t)b * LL + row0) * HDIM;

    u64 acc[4][SS];
#pragma unroll
    for (int r = 0; r < 4; r++)
#pragma unroll
        for (int s = 0; s < SS; s++) acc[r][s] = 0ull;

#pragma unroll 2
    for (int c = 0; c < 16; c++) {
        int h = c * 128 + lane * 4;
        ulonglong2 x2[4];
#pragma unroll
        for (int r = 0; r < 4; r++)
            x2[r] = *reinterpret_cast<const ulonglong2*>(xr + (size_t)r * HDIM + h);
#pragma unroll
        for (int s = 0; s < SS; s++) {
            ulonglong2 k2 = *reinterpret_cast<const ulonglong2*>(skk + s * HDIM + h);
#pragma unroll
            for (int r = 0; r < 4; r++) {
                acc[r][s] = ffma2(x2[r].x, k2.x, acc[r][s]);
                acc[r][s] = ffma2(x2[r].y, k2.y, acc[r][s]);
            }
        }
    }

    float p[4][SS];
#pragma unroll
    for (int r = 0; r < 4; r++)
#pragma unroll
        for (int s = 0; s < SS; s++)
            p[r][s] = warp_sum(hsum2(acc[r][s]));

#pragma unroll
    for (int r = 0; r < 4; r++) {
        float m = p[r][0];
#pragma unroll
        for (int s = 1; s < SS; s++) m = fmaxf(m, p[r][s]);
        float sum = 0.f;
#pragma unroll
        for (int s = 0; s < SS; s++) {
            float e = __expf(p[r][s] - m);
            p[r][s] = e;
            sum += e;
        }
        float inv = alpha / sum;
#pragma unroll
        for (int s = 0; s < SS; s++) p[r][s] *= inv;
    }

    u64 pp[4][SS];
#pragma unroll
    for (int r = 0; r < 4; r++)
#pragma unroll
        for (int s = 0; s < SS; s++) pp[r][s] = pack2(p[r][s], p[r][s]);

#pragma unroll 2
    for (int c = 0; c < 16; c++) {
        int h = c * 128 + lane * 4;
        ulonglong2 y2[4];
#pragma unroll
        for (int r = 0; r < 4; r++)
            y2[r] = *reinterpret_cast<const ulonglong2*>(xr + (size_t)r * HDIM + h);
#pragma unroll
        for (int s = 0; s < SS; s++) {
            ulonglong2 v2 = *reinterpret_cast<const ulonglong2*>(svo + s * HDIM + h);
#pragma unroll
            for (int r = 0; r < 4; r++) {
                y2[r].x = ffma2(pp[r][s], v2.x, y2[r].x);
                y2[r].y = ffma2(pp[r][s], v2.y, y2[r].y);
            }
        }
#pragma unroll
        for (int r = 0; r < 4; r++)
            stcs16(orow + (size_t)r * HDIM + h, y2[r]);
    }
}

extern "C" void kernel_launch(void* const* d_in, const int* in_sizes, int n_in,
                              void* d_out, int out_size)
{
    const float* x     = (const float*)d_in[0];  // h_english [4,4096,2048]
    const float* y     = (const float*)d_in[1];  // h_lojban  [4,10,2048]
    const float* wq    = (const float*)d_in[2];
    const float* wk    = (const float*)d_in[3];
    const float* wv    = (const float*)d_in[4];
    const float* wo    = (const float*)d_in[5];
    const float* alpha = (const float*)d_in[6];
    float* out = (float*)d_out;

    (void)cudaFuncSetAttribute(prep1_mma, cudaFuncAttributeMaxDynamicSharedMemorySize, SM_TOT);
    (void)cudaFuncSetAttribute(prep2_mma, cudaFuncAttributeMaxDynamicSharedMemorySize, SM_TOT);
    (void)cudaFuncSetAttribute(main_kernel, cudaFuncAttributeMaxDynamicSharedMemorySize,
                               2 * SS * HDIM * (int)sizeof(float));

    // Phase 1 (HMMA): kvec/vvec partials (8 k-splits), then reduce
    prep1_mma<<<256, 256, SM_TOT>>>(wk, wv, y);
    reduce1_kernel<<<2 * (TEN / 4) / 256, 256>>>();
    // Phase 2 (HMMA): vo partials + kk partials, then reduce (+scale)
    prep2_mma<<<256, 256, SM_TOT>>>(wo, wq);
    reduce2_kernel<<<2 * (TEN / 4) / 256, 256>>>();
    // Fused attention-apply (R14 config)
    main_kernel<<<dim3(LL / 64, BB), 512, 2 * SS * HDIM * sizeof(float)>>>(x, alpha, out);
}